// round 1
// baseline (speedup 1.0000x reference)
#include <cuda_runtime.h>
#include <cstdint>

// Problem constants (fixed shapes per reference)
#define BB 4
#define CC 64
#define DPP 32
#define HPP 32
#define WPP 32
#define DD 64
#define HH 64
#define WW 64
#define NCHAN (BB*CC)                    // 256
#define POOL_PER_CHAN (DPP*HPP*WPP)      // 32768
#define OUT_PER_CHAN (DD*HH*WW)          // 262144
#define S_TOTAL ((float)OUT_PER_CHAN)    // 262144.0

// Gating scalars, one per (b,c) channel. __device__ global: no allocation.
__device__ float d_gating[NCHAN];

// ---------------------------------------------------------------------------
// Kernel 1: per-channel sum(silu(pooled)) -> log_sigmoid(mean)
// 256 blocks (one per channel), 256 threads each, float4 vectorized loads.
// ---------------------------------------------------------------------------
__global__ __launch_bounds__(256) void gating_kernel(const float* __restrict__ pooled) {
    const int bc = blockIdx.x;
    const float4* __restrict__ p =
        reinterpret_cast<const float4*>(pooled + (size_t)bc * POOL_PER_CHAN);

    float s = 0.0f;
    // 32768 floats = 8192 float4 per channel; 256 threads -> 32 iters each.
    #pragma unroll 4
    for (int i = threadIdx.x; i < POOL_PER_CHAN / 4; i += 256) {
        float4 v = p[i];
        s += v.x * (1.0f / (1.0f + __expf(-v.x)));
        s += v.y * (1.0f / (1.0f + __expf(-v.y)));
        s += v.z * (1.0f / (1.0f + __expf(-v.z)));
        s += v.w * (1.0f / (1.0f + __expf(-v.w)));
    }

    // warp reduce
    #pragma unroll
    for (int off = 16; off > 0; off >>= 1)
        s += __shfl_xor_sync(0xFFFFFFFFu, s, off);

    __shared__ float sh[8];
    const int lane = threadIdx.x & 31;
    const int wid  = threadIdx.x >> 5;
    if (lane == 0) sh[wid] = s;
    __syncthreads();
    if (wid == 0) {
        float t = (lane < 8) ? sh[lane] : 0.0f;
        #pragma unroll
        for (int off = 4; off > 0; off >>= 1)
            t += __shfl_xor_sync(0xFFFFFFFFu, t, off);
        if (lane == 0) {
            float m = t / S_TOTAL;
            // stable log_sigmoid(m) = min(m,0) - log1p(exp(-|m|))
            float g = fminf(m, 0.0f) - log1pf(__expf(-fabsf(m)));
            d_gating[bc] = g;
        }
    }
}

// ---------------------------------------------------------------------------
// Kernel 2: dense unpool + gate.
// Each thread writes one float4 (4 consecutive wo == 2 pooling windows along w).
// Output is written fully coalesced; pooled/indices get 4x L2 reuse.
// t (float4 index) layout: [bc(8) | do(6) | ho(6) | wo4(4)]
// ---------------------------------------------------------------------------
__global__ __launch_bounds__(256) void unpool_kernel(const float* __restrict__ pooled,
                                                     const int*   __restrict__ indices,
                                                     float*       __restrict__ out) {
    const unsigned t = blockIdx.x * 256u + threadIdx.x;   // 0 .. 16777215

    const unsigned wo = (t & 15u) << 2;        // 0..60, step 4
    const unsigned ho = (t >> 4) & 63u;
    const unsigned d0 = (t >> 10) & 63u;
    const unsigned bc = t >> 16;               // 0..255 (uniform per block)

    const float g = d_gating[bc];

    const unsigned dp = d0 >> 1;
    const unsigned hp = ho >> 1;
    const unsigned wp = wo >> 1;               // even

    const size_t pbase = ((size_t)bc * DPP + dp) * (HPP * WPP) + hp * WPP + wp;

    const int2   idx = *reinterpret_cast<const int2*>(indices + pbase);
    const float2 pv  = *reinterpret_cast<const float2*>(pooled + pbase);

    const int base = (int)((d0 * HH + ho) * WW + wo);     // flat spatial pos of out.x

    float4 o;
    const float v0 = pv.x * g;
    const float v1 = pv.y * g;
    o.x = (idx.x == base + 0) ? v0 : 0.0f;
    o.y = (idx.x == base + 1) ? v0 : 0.0f;
    o.z = (idx.y == base + 2) ? v1 : 0.0f;
    o.w = (idx.y == base + 3) ? v1 : 0.0f;

    reinterpret_cast<float4*>(out)[t] = o;
}

// ---------------------------------------------------------------------------
extern "C" void kernel_launch(void* const* d_in, const int* in_sizes, int n_in,
                              void* d_out, int out_size) {
    const float* pooled  = (const float*)d_in[0];
    const int*   indices = (const int*)d_in[1];
    float*       out     = (float*)d_out;

    gating_kernel<<<NCHAN, 256>>>(pooled);

    // total float4 outputs: 4*64*64*64*64/4 = 16,777,216 -> 65536 blocks
    unpool_kernel<<<(BB*CC*DD*HH*WW) / 4 / 256, 256>>>(pooled, indices, out);
}

// round 2
// speedup vs baseline: 1.1801x; 1.1801x over previous
#include <cuda_runtime.h>
#include <cstdint>

// Fixed shapes: pooled/indices [4,64,32,32,32], out [4,64,64,64,64]
#define NCHAN 256
#define POOL_PER_CHAN 32768
#define SLOTS 8                      // partial-sum slots per channel
#define S_TOTAL 262144.0f

// Partial silu-sums: slot layout d_partial[bc*8 + slot]. Every slot is
// rewritten on every call -> deterministic, no zeroing needed.
__device__ float d_partial[NCHAN * SLOTS];

// ---------------------------------------------------------------------------
// Kernel 1: partial sum(silu(pooled)) per 4096-element chunk.
// 2048 blocks x 256 threads; block b owns floats [b*4096, (b+1)*4096).
// ---------------------------------------------------------------------------
__global__ __launch_bounds__(256) void gating_partial(const float* __restrict__ pooled) {
    const float4* __restrict__ p =
        reinterpret_cast<const float4*>(pooled) + (size_t)blockIdx.x * 1024;

    float s = 0.0f;
    #pragma unroll
    for (int i = 0; i < 4; i++) {
        float4 v = p[threadIdx.x + i * 256];
        s += v.x * (1.0f / (1.0f + __expf(-v.x)));
        s += v.y * (1.0f / (1.0f + __expf(-v.y)));
        s += v.z * (1.0f / (1.0f + __expf(-v.z)));
        s += v.w * (1.0f / (1.0f + __expf(-v.w)));
    }

    #pragma unroll
    for (int off = 16; off > 0; off >>= 1)
        s += __shfl_xor_sync(0xFFFFFFFFu, s, off);

    __shared__ float sh[8];
    const int lane = threadIdx.x & 31;
    const int wid  = threadIdx.x >> 5;
    if (lane == 0) sh[wid] = s;
    __syncthreads();
    if (wid == 0) {
        float t = (lane < 8) ? sh[lane] : 0.0f;
        #pragma unroll
        for (int off = 4; off > 0; off >>= 1)
            t += __shfl_xor_sync(0xFFFFFFFFu, t, off);
        if (lane == 0) d_partial[blockIdx.x] = t;
    }
}

// ---------------------------------------------------------------------------
// Kernel 2: dense unpool + gate. Each thread produces 8 consecutive wo
// (= 4 pooling windows along w): int4 + float4 load, two float4 streaming
// stores. Gating finalized once per block from the 8 partials.
// u (8-output index) layout: [bc(8) | do(6) | ho(6) | wo8(3)]
// ---------------------------------------------------------------------------
__global__ __launch_bounds__(256) void unpool_kernel(const float* __restrict__ pooled,
                                                     const int*   __restrict__ indices,
                                                     float*       __restrict__ out) {
    const unsigned bc = blockIdx.x >> 7;          // 128 blocks per channel

    __shared__ float gs;
    if (threadIdx.x == 0) {
        const float* pp = d_partial + bc * SLOTS;
        float t = 0.0f;
        #pragma unroll
        for (int j = 0; j < SLOTS; j++) t += pp[j];
        float m = t / S_TOTAL;
        gs = fminf(m, 0.0f) - log1pf(__expf(-fabsf(m)));   // log_sigmoid(m)
    }
    __syncthreads();
    const float g = gs;

    const unsigned u  = blockIdx.x * 256u + threadIdx.x;   // 0 .. 8388607
    const unsigned wo = (u & 7u) << 3;           // 0..56, step 8
    const unsigned ho = (u >> 3) & 63u;
    const unsigned d0 = (u >> 9) & 63u;

    const unsigned pbase = bc * POOL_PER_CHAN + (d0 >> 1) * 1024u + (ho >> 1) * 32u + (wo >> 1);

    const int4   idx = *reinterpret_cast<const int4*>(indices + pbase);
    const float4 pv  = *reinterpret_cast<const float4*>(pooled + pbase);

    const int base = (int)((d0 * 64u + ho) * 64u + wo);

    const float v0 = pv.x * g, v1 = pv.y * g, v2 = pv.z * g, v3 = pv.w * g;

    float4 a, b;
    a.x = (idx.x == base + 0) ? v0 : 0.0f;
    a.y = (idx.x == base + 1) ? v0 : 0.0f;
    a.z = (idx.y == base + 2) ? v1 : 0.0f;
    a.w = (idx.y == base + 3) ? v1 : 0.0f;
    b.x = (idx.z == base + 4) ? v2 : 0.0f;
    b.y = (idx.z == base + 5) ? v2 : 0.0f;
    b.z = (idx.w == base + 6) ? v3 : 0.0f;
    b.w = (idx.w == base + 7) ? v3 : 0.0f;

    float4* o = reinterpret_cast<float4*>(out) + 2u * u;
    __stcs(o + 0, a);        // streaming store: write-once data, evict-first
    __stcs(o + 1, b);
}

// ---------------------------------------------------------------------------
extern "C" void kernel_launch(void* const* d_in, const int* in_sizes, int n_in,
                              void* d_out, int out_size) {
    const float* pooled  = (const float*)d_in[0];
    const int*   indices = (const int*)d_in[1];
    float*       out     = (float*)d_out;

    gating_partial<<<NCHAN * SLOTS, 256>>>(pooled);          // 2048 blocks
    unpool_kernel<<<32768, 256>>>(pooled, indices, out);     // 8M threads x 8 outputs
}

// round 3
// speedup vs baseline: 1.4154x; 1.1994x over previous
#include <cuda_runtime.h>
#include <cstdint>

// Fixed shapes: pooled/indices [4,64,32,32,32], out [4,64,64,64,64]
#define NCHAN 256
#define POOL_PER_CHAN 32768
#define SLOTS 8
#define S_TOTAL 262144.0f

__device__ float d_partial[NCHAN * SLOTS];

// ---------------------------------------------------------------------------
// Kernel 1: partial sum(silu(pooled)), 2048 blocks x 256 thr, 4 float4/thr.
// ---------------------------------------------------------------------------
__global__ __launch_bounds__(256) void gating_partial(const float* __restrict__ pooled) {
    const float4* __restrict__ p =
        reinterpret_cast<const float4*>(pooled) + (size_t)blockIdx.x * 1024;

    float s = 0.0f;
    #pragma unroll
    for (int i = 0; i < 4; i++) {
        float4 v = __ldg(&p[threadIdx.x + i * 256]);
        s += v.x * (1.0f / (1.0f + __expf(-v.x)));
        s += v.y * (1.0f / (1.0f + __expf(-v.y)));
        s += v.z * (1.0f / (1.0f + __expf(-v.z)));
        s += v.w * (1.0f / (1.0f + __expf(-v.w)));
    }

    #pragma unroll
    for (int off = 16; off > 0; off >>= 1)
        s += __shfl_xor_sync(0xFFFFFFFFu, s, off);

    __shared__ float sh[8];
    const int lane = threadIdx.x & 31;
    const int wid  = threadIdx.x >> 5;
    if (lane == 0) sh[wid] = s;
    __syncthreads();
    if (wid == 0) {
        float t = (lane < 8) ? sh[lane] : 0.0f;
        #pragma unroll
        for (int off = 4; off > 0; off >>= 1)
            t += __shfl_xor_sync(0xFFFFFFFFu, t, off);
        if (lane == 0) d_partial[blockIdx.x] = t;
    }
}

// ---------------------------------------------------------------------------
// Kernel 2: dense unpool + gate. 8 consecutive wo per thread (4 windows):
// int4 + float4 loads, ONE 256-bit store (st.global.v8.f32, sm_100a+).
// u layout: [bc(8) | do(6) | ho(6) | wo8(3)]
// ---------------------------------------------------------------------------
__global__ __launch_bounds__(256) void unpool_kernel(const float* __restrict__ pooled,
                                                     const int*   __restrict__ indices,
                                                     float*       __restrict__ out) {
    const unsigned bc = blockIdx.x >> 7;           // 128 blocks per channel

    __shared__ float gs;
    if (threadIdx.x == 0) {
        const float* pp = d_partial + bc * SLOTS;
        float t = 0.0f;
        #pragma unroll
        for (int j = 0; j < SLOTS; j++) t += pp[j];
        float m = t / S_TOTAL;
        gs = fminf(m, 0.0f) - log1pf(__expf(-fabsf(m)));   // log_sigmoid(m)
    }
    __syncthreads();
    const float g = gs;

    const unsigned u  = blockIdx.x * 256u + threadIdx.x;   // 0 .. 8388607
    const unsigned wo = (u & 7u) << 3;            // 0..56, step 8
    const unsigned ho = (u >> 3) & 63u;
    const unsigned d0 = (u >> 9) & 63u;

    const unsigned pbase = bc * POOL_PER_CHAN + (d0 >> 1) * 1024u + (ho >> 1) * 32u + (wo >> 1);

    const int4   idx = __ldg(reinterpret_cast<const int4*>(indices + pbase));
    const float4 pv  = __ldg(reinterpret_cast<const float4*>(pooled + pbase));

    const int base = (int)((d0 * 64u + ho) * 64u + wo);

    const float v0 = pv.x * g, v1 = pv.y * g, v2 = pv.z * g, v3 = pv.w * g;

    float o0 = (idx.x == base + 0) ? v0 : 0.0f;
    float o1 = (idx.x == base + 1) ? v0 : 0.0f;
    float o2 = (idx.y == base + 2) ? v1 : 0.0f;
    float o3 = (idx.y == base + 3) ? v1 : 0.0f;
    float o4 = (idx.z == base + 4) ? v2 : 0.0f;
    float o5 = (idx.z == base + 5) ? v2 : 0.0f;
    float o6 = (idx.w == base + 6) ? v3 : 0.0f;
    float o7 = (idx.w == base + 7) ? v3 : 0.0f;

    float* optr = out + 8ull * u;                 // 32B-aligned
    asm volatile(
        "st.global.v8.f32 [%0], {%1, %2, %3, %4, %5, %6, %7, %8};"
        :: "l"(optr),
           "f"(o0), "f"(o1), "f"(o2), "f"(o3),
           "f"(o4), "f"(o5), "f"(o6), "f"(o7)
        : "memory");
}

// ---------------------------------------------------------------------------
extern "C" void kernel_launch(void* const* d_in, const int* in_sizes, int n_in,
                              void* d_out, int out_size) {
    const float* pooled  = (const float*)d_in[0];
    const int*   indices = (const int*)d_in[1];
    float*       out     = (float*)d_out;

    gating_partial<<<NCHAN * SLOTS, 256>>>(pooled);          // 2048 blocks
    unpool_kernel<<<32768, 256>>>(pooled, indices, out);     // 8M thr x 8 outputs
}

// round 4
// speedup vs baseline: 1.4669x; 1.0364x over previous
#include <cuda_runtime.h>
#include <cstdint>

// Fixed shapes: pooled/indices [4,64,32,32,32], out [4,64,64,64,64]
#define NCHAN 256
#define POOL_PER_CHAN 32768
#define SLOTS 8
#define S_TOTAL 262144.0f

__device__ float d_partial[NCHAN * SLOTS];

// ---------------------------------------------------------------------------
// Kernel 1: partial sum(silu(pooled)), 2048 blocks x 256 thr, 4 float4/thr.
// ---------------------------------------------------------------------------
__global__ __launch_bounds__(256) void gating_partial(const float* __restrict__ pooled) {
    const float4* __restrict__ p =
        reinterpret_cast<const float4*>(pooled) + (size_t)blockIdx.x * 1024;

    float s = 0.0f;
    #pragma unroll
    for (int i = 0; i < 4; i++) {
        float4 v = __ldg(&p[threadIdx.x + i * 256]);
        s += v.x * (1.0f / (1.0f + __expf(-v.x)));
        s += v.y * (1.0f / (1.0f + __expf(-v.y)));
        s += v.z * (1.0f / (1.0f + __expf(-v.z)));
        s += v.w * (1.0f / (1.0f + __expf(-v.w)));
    }

    #pragma unroll
    for (int off = 16; off > 0; off >>= 1)
        s += __shfl_xor_sync(0xFFFFFFFFu, s, off);

    __shared__ float sh[8];
    const int lane = threadIdx.x & 31;
    const int wid  = threadIdx.x >> 5;
    if (lane == 0) sh[wid] = s;
    __syncthreads();
    if (wid == 0) {
        float t = (lane < 8) ? sh[lane] : 0.0f;
        #pragma unroll
        for (int off = 4; off > 0; off >>= 1)
            t += __shfl_xor_sync(0xFFFFFFFFu, t, off);
        if (lane == 0) d_partial[blockIdx.x] = t;
    }
}

// ---------------------------------------------------------------------------
// Kernel 2: dense unpool + gate. 16 consecutive wo per thread (8 windows):
// 2x(int4 + float4) loads, TWO 256-bit stores. Both loads issued up front
// for MLP; stores are back-to-back and independent.
// u (16-output index) layout: [bc(8) | do(6) | ho(6) | wo16(2)]
// ---------------------------------------------------------------------------
__global__ __launch_bounds__(256) void unpool_kernel(const float* __restrict__ pooled,
                                                     const int*   __restrict__ indices,
                                                     float*       __restrict__ out) {
    const unsigned bc = blockIdx.x >> 6;           // 64 blocks per channel

    __shared__ float gs;
    if (threadIdx.x == 0) {
        const float* pp = d_partial + bc * SLOTS;
        float t = 0.0f;
        #pragma unroll
        for (int j = 0; j < SLOTS; j++) t += pp[j];
        float m = t / S_TOTAL;
        gs = fminf(m, 0.0f) - log1pf(__expf(-fabsf(m)));   // log_sigmoid(m)
    }
    __syncthreads();
    const float g = gs;

    const unsigned u  = blockIdx.x * 256u + threadIdx.x;   // 0 .. 4194303
    const unsigned wo = (u & 3u) << 4;            // 0,16,32,48
    const unsigned ho = (u >> 2) & 63u;
    const unsigned d0 = (u >> 8) & 63u;

    const unsigned pbase = bc * POOL_PER_CHAN + (d0 >> 1) * 1024u + (ho >> 1) * 32u + (wo >> 1);

    // Issue all four loads before any consumption (MLP=4).
    const int4   ia = __ldg(reinterpret_cast<const int4*>(indices + pbase));
    const int4   ib = __ldg(reinterpret_cast<const int4*>(indices + pbase + 4));
    const float4 pa = __ldg(reinterpret_cast<const float4*>(pooled + pbase));
    const float4 pb = __ldg(reinterpret_cast<const float4*>(pooled + pbase + 4));

    const int base = (int)((d0 * 64u + ho) * 64u + wo);

    const float a0 = pa.x * g, a1 = pa.y * g, a2 = pa.z * g, a3 = pa.w * g;
    const float b0 = pb.x * g, b1 = pb.y * g, b2 = pb.z * g, b3 = pb.w * g;

    float o0  = (ia.x == base +  0) ? a0 : 0.0f;
    float o1  = (ia.x == base +  1) ? a0 : 0.0f;
    float o2  = (ia.y == base +  2) ? a1 : 0.0f;
    float o3  = (ia.y == base +  3) ? a1 : 0.0f;
    float o4  = (ia.z == base +  4) ? a2 : 0.0f;
    float o5  = (ia.z == base +  5) ? a2 : 0.0f;
    float o6  = (ia.w == base +  6) ? a3 : 0.0f;
    float o7  = (ia.w == base +  7) ? a3 : 0.0f;
    float o8  = (ib.x == base +  8) ? b0 : 0.0f;
    float o9  = (ib.x == base +  9) ? b0 : 0.0f;
    float o10 = (ib.y == base + 10) ? b1 : 0.0f;
    float o11 = (ib.y == base + 11) ? b1 : 0.0f;
    float o12 = (ib.z == base + 12) ? b2 : 0.0f;
    float o13 = (ib.z == base + 13) ? b2 : 0.0f;
    float o14 = (ib.w == base + 14) ? b3 : 0.0f;
    float o15 = (ib.w == base + 15) ? b3 : 0.0f;

    float* optr = out + 16ull * u;                // 64B-aligned
    asm volatile(
        "st.global.v8.f32 [%0], {%1, %2, %3, %4, %5, %6, %7, %8};"
        :: "l"(optr),
           "f"(o0), "f"(o1), "f"(o2), "f"(o3),
           "f"(o4), "f"(o5), "f"(o6), "f"(o7)
        : "memory");
    asm volatile(
        "st.global.v8.f32 [%0], {%1, %2, %3, %4, %5, %6, %7, %8};"
        :: "l"(optr + 8),
           "f"(o8),  "f"(o9),  "f"(o10), "f"(o11),
           "f"(o12), "f"(o13), "f"(o14), "f"(o15)
        : "memory");
}

// ---------------------------------------------------------------------------
extern "C" void kernel_launch(void* const* d_in, const int* in_sizes, int n_in,
                              void* d_out, int out_size) {
    const float* pooled  = (const float*)d_in[0];
    const int*   indices = (const int*)d_in[1];
    float*       out     = (float*)d_out;

    gating_partial<<<NCHAN * SLOTS, 256>>>(pooled);          // 2048 blocks
    unpool_kernel<<<16384, 256>>>(pooled, indices, out);     // 4M thr x 16 outputs
}

// round 6
// speedup vs baseline: 1.5037x; 1.0251x over previous
#include <cuda_runtime.h>
#include <cstdint>

// Fixed shapes: pooled/indices [4,64,32,32,32], out [4,64,64,64,64]
#define NCHAN 256
#define POOL_PER_CHAN 32768
#define SLOTS 8
#define S_TOTAL 262144.0f

__device__ float d_partial[NCHAN * SLOTS];

// ---------------------------------------------------------------------------
// Kernel 1 (primary): partial sum(silu(pooled)), 2048 blocks x 256 thr.
// Triggers programmatic launch completion at entry so the unpool kernel can
// begin scheduling immediately; the consumer grid-syncs before reading
// d_partial, so correctness only needs this grid to COMPLETE before that sync
// returns (guaranteed by PDL semantics).
// ---------------------------------------------------------------------------
__global__ __launch_bounds__(256) void gating_partial(const float* __restrict__ pooled) {
    cudaTriggerProgrammaticLaunchCompletion();

    const float4* __restrict__ p =
        reinterpret_cast<const float4*>(pooled) + (size_t)blockIdx.x * 1024;

    float s = 0.0f;
    #pragma unroll
    for (int i = 0; i < 4; i++) {
        float4 v = __ldg(&p[threadIdx.x + i * 256]);
        s += v.x * (1.0f / (1.0f + __expf(-v.x)));
        s += v.y * (1.0f / (1.0f + __expf(-v.y)));
        s += v.z * (1.0f / (1.0f + __expf(-v.z)));
        s += v.w * (1.0f / (1.0f + __expf(-v.w)));
    }

    #pragma unroll
    for (int off = 16; off > 0; off >>= 1)
        s += __shfl_xor_sync(0xFFFFFFFFu, s, off);

    __shared__ float sh[8];
    const int lane = threadIdx.x & 31;
    const int wid  = threadIdx.x >> 5;
    if (lane == 0) sh[wid] = s;
    __syncthreads();
    if (wid == 0) {
        float t = (lane < 8) ? sh[lane] : 0.0f;
        #pragma unroll
        for (int off = 4; off > 0; off >>= 1)
            t += __shfl_xor_sync(0xFFFFFFFFu, t, off);
        if (lane == 0) d_partial[blockIdx.x] = t;
    }
}

// ---------------------------------------------------------------------------
// Kernel 2 (secondary, PDL): dense unpool + gate. 16 consecutive wo per
// thread (8 windows): 2x(int4+float4) loads issued BEFORE the grid-dependency
// sync (they don't depend on kernel 1), then gating finalized, then two
// 256-bit stores.
// u (16-output index) layout: [bc(8) | do(6) | ho(6) | wo16(2)]
// ---------------------------------------------------------------------------
__global__ __launch_bounds__(256) void unpool_kernel(const float* __restrict__ pooled,
                                                     const int*   __restrict__ indices,
                                                     float*       __restrict__ out) {
    const unsigned bc = blockIdx.x >> 6;           // 64 blocks per channel

    const unsigned u  = blockIdx.x * 256u + threadIdx.x;   // 0 .. 4194303
    const unsigned wo = (u & 3u) << 4;            // 0,16,32,48
    const unsigned ho = (u >> 2) & 63u;
    const unsigned d0 = (u >> 8) & 63u;

    const unsigned pbase = bc * POOL_PER_CHAN + (d0 >> 1) * 1024u + (ho >> 1) * 32u + (wo >> 1);

    // Front-issue all loads (independent of the primary kernel).
    const int4   ia = __ldg(reinterpret_cast<const int4*>(indices + pbase));
    const int4   ib = __ldg(reinterpret_cast<const int4*>(indices + pbase + 4));
    const float4 pa = __ldg(reinterpret_cast<const float4*>(pooled + pbase));
    const float4 pb = __ldg(reinterpret_cast<const float4*>(pooled + pbase + 4));

    // Wait for gating_partial grid to complete (PDL dependency point).
    cudaGridDependencySynchronize();

    __shared__ float gs;
    if (threadIdx.x == 0) {
        const float* pp = d_partial + bc * SLOTS;
        float t = 0.0f;
        #pragma unroll
        for (int j = 0; j < SLOTS; j++) t += pp[j];
        float m = t / S_TOTAL;
        gs = fminf(m, 0.0f) - log1pf(__expf(-fabsf(m)));   // log_sigmoid(m)
    }
    __syncthreads();
    const float g = gs;

    const int base = (int)((d0 * 64u + ho) * 64u + wo);

    const float a0 = pa.x * g, a1 = pa.y * g, a2 = pa.z * g, a3 = pa.w * g;
    const float b0 = pb.x * g, b1 = pb.y * g, b2 = pb.z * g, b3 = pb.w * g;

    float o0  = (ia.x == base +  0) ? a0 : 0.0f;
    float o1  = (ia.x == base +  1) ? a0 : 0.0f;
    float o2  = (ia.y == base +  2) ? a1 : 0.0f;
    float o3  = (ia.y == base +  3) ? a1 : 0.0f;
    float o4  = (ia.z == base +  4) ? a2 : 0.0f;
    float o5  = (ia.z == base +  5) ? a2 : 0.0f;
    float o6  = (ia.w == base +  6) ? a3 : 0.0f;
    float o7  = (ia.w == base +  7) ? a3 : 0.0f;
    float o8  = (ib.x == base +  8) ? b0 : 0.0f;
    float o9  = (ib.x == base +  9) ? b0 : 0.0f;
    float o10 = (ib.y == base + 10) ? b1 : 0.0f;
    float o11 = (ib.y == base + 11) ? b1 : 0.0f;
    float o12 = (ib.z == base + 12) ? b2 : 0.0f;
    float o13 = (ib.z == base + 13) ? b2 : 0.0f;
    float o14 = (ib.w == base + 14) ? b3 : 0.0f;
    float o15 = (ib.w == base + 15) ? b3 : 0.0f;

    float* optr = out + 16ull * u;                // 64B-aligned
    asm volatile(
        "st.global.v8.f32 [%0], {%1, %2, %3, %4, %5, %6, %7, %8};"
        :: "l"(optr),
           "f"(o0), "f"(o1), "f"(o2), "f"(o3),
           "f"(o4), "f"(o5), "f"(o6), "f"(o7)
        : "memory");
    asm volatile(
        "st.global.v8.f32 [%0], {%1, %2, %3, %4, %5, %6, %7, %8};"
        :: "l"(optr + 8),
           "f"(o8),  "f"(o9),  "f"(o10), "f"(o11),
           "f"(o12), "f"(o13), "f"(o14), "f"(o15)
        : "memory");
}

// ---------------------------------------------------------------------------
extern "C" void kernel_launch(void* const* d_in, const int* in_sizes, int n_in,
                              void* d_out, int out_size) {
    const float* pooled  = (const float*)d_in[0];
    const int*   indices = (const int*)d_in[1];
    float*       out     = (float*)d_out;

    gating_partial<<<NCHAN * SLOTS, 256>>>(pooled);          // 2048 blocks

    // Secondary launch with Programmatic Stream Serialization (PDL): may begin
    // while gating_partial is still running; cudaGridDependencySynchronize()
    // inside provides the real dependency.
    cudaLaunchConfig_t cfg = {};
    cfg.gridDim  = dim3(16384, 1, 1);
    cfg.blockDim = dim3(256, 1, 1);
    cfg.dynamicSmemBytes = 0;
    cfg.stream = 0;
    cudaLaunchAttribute attr[1];
    attr[0].id = cudaLaunchAttributeProgrammaticStreamSerialization;
    attr[0].val.programmaticStreamSerializationAllowed = 1;
    cfg.attrs = attr;
    cfg.numAttrs = 1;
    cudaLaunchKernelEx(&cfg, unpool_kernel, pooled, indices, out);
}